// round 10
// baseline (speedup 1.0000x reference)
#include <cuda_runtime.h>
#include <cuda_bf16.h>
#include <cstdint>

// ---------------------------------------------------------------------------
// CAttention B=8,N=2048,DIM=512. GEMMs: mma.sync m16n8k8 tf32, cp.async 3-stage
// pipeline, XOR-swizzled smem, ldmatrix fragments, pre-rounded tf32 operands.
// Canonical GEMM: D[M,N] = alpha * A[M,K] @ B[N,K]^T (+bias), K=512.
// ---------------------------------------------------------------------------

#define BATCH 8
#define SEQ   2048
#define DIM   512
#define ROWS  (BATCH*SEQ)
#define NCLUST 16
#define SCALE_F 0.125f
#define EPS_F  1e-6f

__device__ float g_qk[(size_t)ROWS * 1024];
__device__ float g_v[(size_t)ROWS * DIM];
__device__ float g_out3[(size_t)ROWS * DIM];
__device__ float g_xr[(size_t)ROWS * DIM];      // tf32-rounded x_token
__device__ float g_wqkT[1024 * 512];
__device__ float g_wvT[512 * 512];
__device__ float g_wprojT[512 * 512];
__device__ float g_e[BATCH * SEQ];
__device__ float g_S[BATCH * NCLUST];
__device__ float g_wsum[BATCH * NCLUST * DIM];
__device__ float g_vpart[BATCH * NCLUST * DIM];
__device__ float g_f[BATCH * NCLUST * DIM];
__device__ int   g_shuffle[BATCH * SEQ];
__device__ int   g_restore[BATCH * SEQ];
__device__ int   g_ssorted[BATCH * SEQ];
__device__ int   g_offs[BATCH * 17];

template<int SEL>
__device__ __forceinline__ const float* pick_c(const float* p) {
    if (SEL == 0) return g_qk;
    if (SEL == 1) return g_qk + DIM;
    if (SEL == 2) return g_v;
    if (SEL == 3) return g_out3;
    if (SEL == 4) return g_wqkT;
    if (SEL == 5) return g_wvT;
    if (SEL == 6) return g_wprojT;
    if (SEL == 7) return g_xr;
    return p;
}
template<int SEL>
__device__ __forceinline__ float* pick_m(float* p) {
    if (SEL == 0) return g_qk;
    if (SEL == 2) return g_v;
    if (SEL == 3) return g_out3;
    if (SEL == 4) return g_wqkT;
    if (SEL == 5) return g_wvT;
    if (SEL == 6) return g_wprojT;
    if (SEL == 7) return g_xr;
    return p;
}

__device__ __forceinline__ uint32_t f2tf32(float f) {
    uint32_t r;
    asm("cvt.rna.tf32.f32 %0, %1;" : "=r"(r) : "f"(f));
    return r;
}
__device__ __forceinline__ float roundtf(float f) {
    return __uint_as_float(f2tf32(f));
}
__device__ __forceinline__ uint32_t smem_u32(const void* p) {
    uint32_t a;
    asm("{ .reg .u64 t; cvta.to.shared.u64 t, %1; cvt.u32.u64 %0, t; }"
        : "=r"(a) : "l"(p));
    return a;
}

#define LDSM_X4(r, a) \
    asm volatile("ldmatrix.sync.aligned.m8n8.x4.shared.b16 {%0,%1,%2,%3}, [%4];" \
        : "=r"((r)[0]), "=r"((r)[1]), "=r"((r)[2]), "=r"((r)[3]) : "r"(a))
#define CPA16(dst, src) \
    asm volatile("cp.async.cg.shared.global [%0], [%1], 16;" \
        :: "r"(dst), "l"(src) : "memory")
#define CPA_COMMIT() asm volatile("cp.async.commit_group;" ::: "memory")
#define CPA_WAIT1()  asm volatile("cp.async.wait_group 1;" ::: "memory")

__device__ __forceinline__ void mma_tf32(float* c, const uint32_t* a,
                                         uint32_t b0, uint32_t b1) {
    asm volatile(
        "mma.sync.aligned.m16n8k8.row.col.f32.tf32.tf32.f32 "
        "{%0,%1,%2,%3}, {%4,%5,%6,%7}, {%8,%9}, {%0,%1,%2,%3};"
        : "+f"(c[0]), "+f"(c[1]), "+f"(c[2]), "+f"(c[3])
        : "r"(a[0]), "r"(a[1]), "r"(a[2]), "r"(a[3]), "r"(b0), "r"(b1));
}

// ------------------------- tf32 mma.sync GEMM -------------------------------
// BM=BN=128, BK=16, 128 threads (4 warps, 2x2), warp tile 64x64 (4x8 atoms).
// 3-stage cp.async pipeline; smem 3 x (A 8KB + B 8KB) = 48KB static.
// Swizzle: 16B chunk index ch' = ch ^ ((row>>1)&3), row stride 64B.
#define NITK 32   // K = 512 / BK 16

template<bool BIAS, bool CVT, int ASEL, int BSEL, int CSEL>
__global__ __launch_bounds__(128)
void gemm_mma(const float* __restrict__ Ain, const float* __restrict__ Bin,
              float* __restrict__ Cin, const float* __restrict__ bias,
              int lda, int ldb, int ldc,
              size_t sA, size_t sB, size_t sC, float alpha)
{
    __shared__ uint32_t sm[3][2][128 * 16];

    const float* A = pick_c<ASEL>(Ain) + (size_t)blockIdx.z * sA;
    const float* B = pick_c<BSEL>(Bin) + (size_t)blockIdx.z * sB;
    float*       C = pick_m<CSEL>(Cin) + (size_t)blockIdx.z * sC;

    const int m0 = blockIdx.y * 128;
    const int n0 = blockIdx.x * 128;
    const int tid  = threadIdx.x;
    const int warp = tid >> 5, lane = tid & 31;
    const int wm = (warp & 1) * 64;
    const int wn = (warp >> 1) * 64;
    const int gid = lane >> 2, tig = lane & 3;
    const int i8 = lane & 7, mtx = lane >> 3;

    const uint32_t smbase = smem_u32(sm);

    // LDSM byte-offset components (within one operand buffer)
    int rowA[4], rsA[4];
#pragma unroll
    for (int am = 0; am < 4; ++am) {
        int r = wm + am * 16 + i8 + ((mtx & 1) << 3);
        rowA[am] = r * 64;
        rsA[am] = (r >> 1) & 3;
    }
    const int csA = mtx >> 1;
    int rowB[4], rsB[4];
#pragma unroll
    for (int bp = 0; bp < 4; ++bp) {
        int r = wn + bp * 16 + i8 + ((mtx >> 1) << 3);
        rowB[bp] = r * 64;
        rsB[bp] = (r >> 1) & 3;
    }
    const int csB = mtx & 1;

    float acc[4][8][4];
#pragma unroll
    for (int i = 0; i < 4; ++i)
#pragma unroll
        for (int j = 0; j < 8; ++j)
#pragma unroll
            for (int r = 0; r < 4; ++r) acc[i][j][r] = 0.f;

    auto stage_tile = [&](int kt, int s) {
        const int k0 = kt * 16;
        const uint32_t bA = smbase + (uint32_t)s * 16384u;
        const uint32_t bB = bA + 8192u;
#pragma unroll
        for (int l = 0; l < 4; ++l) {
            int idx = tid + l * 128;          // 0..511
            int row = idx >> 2, ch = idx & 3;
            uint32_t woff = (uint32_t)(row * 64 + (((ch ^ ((row >> 1) & 3))) << 4));
            CPA16(bA + woff, A + (size_t)(m0 + row) * lda + k0 + ch * 4);
            CPA16(bB + woff, B + (size_t)(n0 + row) * ldb + k0 + ch * 4);
        }
        CPA_COMMIT();
    };

    stage_tile(0, 0);
    stage_tile(1, 1);

    for (int it = 0; it < NITK; ++it) {
        CPA_WAIT1();
        __syncthreads();
        if (it + 2 < NITK) stage_tile(it + 2, (it + 2) % 3);
        else CPA_COMMIT();   // empty group keeps wait_group accounting uniform

        const uint32_t bA = smbase + (uint32_t)(it % 3) * 16384u;
        const uint32_t bB = bA + 8192u;
#pragma unroll
        for (int ks = 0; ks < 2; ++ks) {
            uint32_t af[4][4], bf[4][4];
#pragma unroll
            for (int am = 0; am < 4; ++am)
                LDSM_X4(af[am], bA + rowA[am] + ((((2 * ks + csA) ^ rsA[am])) << 4));
#pragma unroll
            for (int bp = 0; bp < 4; ++bp)
                LDSM_X4(bf[bp], bB + rowB[bp] + ((((2 * ks + csB) ^ rsB[bp])) << 4));
#pragma unroll
            for (int am = 0; am < 4; ++am)
#pragma unroll
                for (int an = 0; an < 8; ++an)
                    mma_tf32(acc[am][an], af[am],
                             bf[an >> 1][(an & 1) * 2], bf[an >> 1][(an & 1) * 2 + 1]);
        }
    }

    // epilogue
#pragma unroll
    for (int am = 0; am < 4; ++am) {
        int row = m0 + wm + am * 16 + gid;
#pragma unroll
        for (int an = 0; an < 8; ++an) {
            int col = n0 + wn + an * 8 + 2 * tig;
            float b0 = 0.f, b1 = 0.f;
            if (BIAS) { b0 = bias[col]; b1 = bias[col + 1]; }
            float2 v0, v1;
            v0.x = acc[am][an][0] * alpha + b0;
            v0.y = acc[am][an][1] * alpha + b1;
            v1.x = acc[am][an][2] * alpha + b0;
            v1.y = acc[am][an][3] * alpha + b1;
            if (CVT) {
                v0.x = roundtf(v0.x); v0.y = roundtf(v0.y);
                v1.x = roundtf(v1.x); v1.y = roundtf(v1.y);
            }
            *reinterpret_cast<float2*>(C + (size_t)row * ldc + col) = v0;
            *reinterpret_cast<float2*>(C + (size_t)(row + 8) * ldc + col) = v1;
        }
    }
}

// ------------------- tf32 round-copy of x_token ----------------------------
__global__ void round_copy(const float4* __restrict__ in)
{
    size_t i = (size_t)blockIdx.x * 256 + threadIdx.x;
    float4 v = in[i];
    v.x = roundtf(v.x); v.y = roundtf(v.y);
    v.z = roundtf(v.z); v.w = roundtf(v.w);
    reinterpret_cast<float4*>(g_xr)[i] = v;
}

// -------------------------- weight transpose (+round) ----------------------
template<int DSTSEL>
__global__ void transpose_k(const float* __restrict__ in, int R, int C)
{
    __shared__ float t[32][33];
    float* out = pick_m<DSTSEL>(nullptr);
    int c0 = blockIdx.x * 32, r0 = blockIdx.y * 32;
    int x = threadIdx.x, y = threadIdx.y;
#pragma unroll
    for (int i = 0; i < 32; i += 8)
        t[y + i][x] = in[(size_t)(r0 + y + i) * C + (c0 + x)];
    __syncthreads();
#pragma unroll
    for (int i = 0; i < 32; i += 8)
        out[(size_t)(c0 + y + i) * R + (r0 + x)] = roundtf(t[x][y + i]);
}

// --------------------- stable counting sort (per batch) --------------------
__global__ void sort_kernel(const int* __restrict__ idx)
{
    int b = blockIdx.x;
    const int* ic = idx + b * SEQ;
    __shared__ int cnt[NCLUST];
    __shared__ int off[NCLUST + 1];
    int t = threadIdx.x;
    if (t < NCLUST) {
        int c = 0;
        for (int i = 0; i < SEQ; ++i) c += (ic[i] == t);
        cnt[t] = c;
    }
    __syncthreads();
    if (t == 0) {
        int a = 0;
        for (int c = 0; c < NCLUST; ++c) { off[c] = a; a += cnt[c]; }
        off[NCLUST] = a;
        for (int c = 0; c <= NCLUST; ++c) g_offs[b * 17 + c] = off[c];
    }
    __syncthreads();
    if (t < NCLUST) {
        int pos = off[t];
        for (int i = 0; i < SEQ; ++i)
            if (ic[i] == t) {
                g_shuffle[b * SEQ + pos] = i;
                g_restore[b * SEQ + i] = pos;
                g_ssorted[b * SEQ + pos] = t;
                pos++;
            }
    }
}

__global__ void ecol_kernel(const float* __restrict__ attn)
{
    int b = blockIdx.y;
    int j = blockIdx.x * 256 + threadIdx.x;
    const int* sh = g_shuffle + b * SEQ;
    int dd = sh[sh[j]];
    g_e[b * SEQ + j] = expf(attn[(size_t)b * SEQ * SEQ + (size_t)dd * SEQ + j]);
}

__global__ void csum_kernel()
{
    int b = blockIdx.y, c = blockIdx.x, d = threadIdx.x;
    const float* vb = g_v + (size_t)b * SEQ * DIM;
    if (c < NCLUST) {
        int j0 = g_offs[b * 17 + c], j1 = g_offs[b * 17 + c + 1];
        float acc = 0.f, se = 0.f;
        for (int j = j0; j < j1; ++j) {
            float w = g_e[b * SEQ + j];
            int row = g_shuffle[b * SEQ + j];
            acc += w * vb[(size_t)row * DIM + d];
            se += w;
        }
        g_wsum[(b * NCLUST + c) * DIM + d] = acc;
        if (d == 0) g_S[b * NCLUST + c] = se;
    } else {
        int p = c - NCLUST;
        float acc = 0.f;
        for (int j = p * 128; j < p * 128 + 128; ++j)
            acc += vb[(size_t)j * DIM + d];
        g_vpart[(b * NCLUST + p) * DIM + d] = acc;
    }
}

__global__ void fcomp_kernel()
{
    int b = blockIdx.y, c = blockIdx.x, d = threadIdx.x;
    float vs = 0.f;
#pragma unroll
    for (int p = 0; p < NCLUST; ++p) vs += g_vpart[(b * NCLUST + p) * DIM + d];
    float w = g_wsum[(b * NCLUST + c) * DIM + d];
    g_f[(b * NCLUST + c) * DIM + d] =
        (w + (EPS_F / (float)SEQ) * vs) / (g_S[b * NCLUST + c] + EPS_F);
}

// out3[b,i,j] = round_tf32( f[ s[b,(r&3)*512+j] ][ r>>2 ] ),  r = restore[b,i]
__global__ void gather_kernel()
{
    __shared__ float sf[NCLUST];
    int b = blockIdx.z, i = blockIdx.y;
    int r = g_restore[b * SEQ + i];
    int d = r >> 2;
    if (threadIdx.x < NCLUST)
        sf[threadIdx.x] = g_f[(b * NCLUST + threadIdx.x) * DIM + d];
    __syncthreads();
    int j = blockIdx.x * 256 + threadIdx.x;
    int cval = g_ssorted[b * SEQ + ((r & 3) << 9) + j];
    g_out3[((size_t)(b * SEQ + i)) * DIM + j] = roundtf(sf[cval]);
}

// ---------------------------------------------------------------------------
extern "C" void kernel_launch(void* const* d_in, const int* in_sizes, int n_in,
                              void* d_out, int out_size)
{
    const float *x_token = nullptr, *Wqk = nullptr, *Wv = nullptr,
                *Wproj = nullptr, *bproj = nullptr;
    const int *idxc = nullptr;
    for (int i = 0; i < n_in; ++i) {
        long s = in_sizes[i];
        if (s == 8388608 && !x_token)      x_token = (const float*)d_in[i];
        else if (s == 16384 && !idxc)      idxc    = (const int*)d_in[i];
        else if (s == 524288 && !Wqk)      Wqk     = (const float*)d_in[i];
        else if (s == 262144) { if (!Wv) Wv = (const float*)d_in[i];
                                else if (!Wproj) Wproj = (const float*)d_in[i]; }
        else if (s == 512 && !bproj)       bproj   = (const float*)d_in[i];
    }
    if (!x_token || !idxc || !Wqk || !Wv || !Wproj || !bproj) return;

    float* xout = (float*)d_out;
    float* attn = xout + (size_t)ROWS * DIM;

    // 0) pre-round operands
    round_copy<<<8192, 256>>>((const float4*)x_token);
    transpose_k<4><<<dim3(1024 / 32, 512 / 32), dim3(32, 8)>>>(Wqk, 512, 1024);
    transpose_k<5><<<dim3(512 / 32, 512 / 32), dim3(32, 8)>>>(Wv, 512, 512);
    transpose_k<6><<<dim3(512 / 32, 512 / 32), dim3(32, 8)>>>(Wproj, 512, 512);

    // 1) qk = xr @ WqkT^T -> g_qk (epilogue-rounded: feeds attn GEMM)
    gemm_mma<false, true, 7, 4, 0><<<dim3(8, 128, 1), 128>>>(
        nullptr, nullptr, nullptr, nullptr, 512, 512, 1024, 0, 0, 0, 1.0f);

    // 2) v = xr @ WvT^T -> g_v (fp32, consumed by csum)
    gemm_mma<false, false, 7, 5, 2><<<dim3(4, 128, 1), 128>>>(
        nullptr, nullptr, nullptr, nullptr, 512, 512, 512, 0, 0, 0, 1.0f);

    // 3) sort
    sort_kernel<<<BATCH, 32>>>(idxc);

    // 4) attn[b] = q[b] @ k[b]^T * SCALE (batched)
    gemm_mma<false, false, 0, 1, -1><<<dim3(16, 16, BATCH), 128>>>(
        nullptr, nullptr, attn, nullptr, 1024, 1024, SEQ,
        (size_t)SEQ * 1024, (size_t)SEQ * 1024, (size_t)SEQ * SEQ, SCALE_F);

    // 5-8) elementwise pipeline
    ecol_kernel<<<dim3(SEQ / 256, BATCH), 256>>>(attn);
    csum_kernel<<<dim3(32, BATCH), DIM>>>();
    fcomp_kernel<<<dim3(NCLUST, BATCH), DIM>>>();
    gather_kernel<<<dim3(DIM / 256, SEQ, BATCH), 256>>>();

    // 9) x_out = out3 @ WprojT^T + bproj
    gemm_mma<true, false, 3, 6, -1><<<dim3(4, 128, 1), 128>>>(
        nullptr, nullptr, xout, bproj, 512, 512, 512, 0, 0, 0, 1.0f);

    (void)out_size;
}

// round 11
// speedup vs baseline: 1.3787x; 1.3787x over previous
#include <cuda_runtime.h>
#include <cuda_bf16.h>
#include <cstdint>

// ---------------------------------------------------------------------------
// CAttention B=8,N=2048,DIM=512. GEMMs: mma.sync m16n8k8 tf32, cp.async 3-stage
// pipeline, XOR-swizzled smem, ldmatrix fragments, pre-rounded tf32 operands.
// 256 threads / 8 warps (2x4), warp tile 64x32 (R8 shape + R9 pipeline).
// Canonical GEMM: D[M,N] = alpha * A[M,K] @ B[N,K]^T (+bias), K=512.
// ---------------------------------------------------------------------------

#define BATCH 8
#define SEQ   2048
#define DIM   512
#define ROWS  (BATCH*SEQ)
#define NCLUST 16
#define SCALE_F 0.125f
#define EPS_F  1e-6f

__device__ float g_qk[(size_t)ROWS * 1024];
__device__ float g_v[(size_t)ROWS * DIM];
__device__ float g_out3[(size_t)ROWS * DIM];
__device__ float g_xr[(size_t)ROWS * DIM];      // tf32-rounded x_token
__device__ float g_wqkT[1024 * 512];
__device__ float g_wvT[512 * 512];
__device__ float g_wprojT[512 * 512];
__device__ float g_e[BATCH * SEQ];
__device__ float g_S[BATCH * NCLUST];
__device__ float g_wsum[BATCH * NCLUST * DIM];
__device__ float g_vpart[BATCH * NCLUST * DIM];
__device__ float g_f[BATCH * NCLUST * DIM];
__device__ int   g_shuffle[BATCH * SEQ];
__device__ int   g_restore[BATCH * SEQ];
__device__ int   g_ssorted[BATCH * SEQ];
__device__ int   g_offs[BATCH * 17];

template<int SEL>
__device__ __forceinline__ const float* pick_c(const float* p) {
    if (SEL == 0) return g_qk;
    if (SEL == 1) return g_qk + DIM;
    if (SEL == 2) return g_v;
    if (SEL == 3) return g_out3;
    if (SEL == 4) return g_wqkT;
    if (SEL == 5) return g_wvT;
    if (SEL == 6) return g_wprojT;
    if (SEL == 7) return g_xr;
    return p;
}
template<int SEL>
__device__ __forceinline__ float* pick_m(float* p) {
    if (SEL == 0) return g_qk;
    if (SEL == 2) return g_v;
    if (SEL == 3) return g_out3;
    if (SEL == 4) return g_wqkT;
    if (SEL == 5) return g_wvT;
    if (SEL == 6) return g_wprojT;
    if (SEL == 7) return g_xr;
    return p;
}

__device__ __forceinline__ uint32_t f2tf32(float f) {
    uint32_t r;
    asm("cvt.rna.tf32.f32 %0, %1;" : "=r"(r) : "f"(f));
    return r;
}
__device__ __forceinline__ float roundtf(float f) {
    return __uint_as_float(f2tf32(f));
}
__device__ __forceinline__ uint32_t smem_u32(const void* p) {
    uint32_t a;
    asm("{ .reg .u64 t; cvta.to.shared.u64 t, %1; cvt.u32.u64 %0, t; }"
        : "=r"(a) : "l"(p));
    return a;
}

#define LDSM_X4(r, a) \
    asm volatile("ldmatrix.sync.aligned.m8n8.x4.shared.b16 {%0,%1,%2,%3}, [%4];" \
        : "=r"((r)[0]), "=r"((r)[1]), "=r"((r)[2]), "=r"((r)[3]) : "r"(a))
#define CPA16(dst, src) \
    asm volatile("cp.async.cg.shared.global [%0], [%1], 16;" \
        :: "r"(dst), "l"(src) : "memory")
#define CPA_COMMIT() asm volatile("cp.async.commit_group;" ::: "memory")
#define CPA_WAIT1()  asm volatile("cp.async.wait_group 1;" ::: "memory")

__device__ __forceinline__ void mma_tf32(float* c, const uint32_t* a,
                                         uint32_t b0, uint32_t b1) {
    asm volatile(
        "mma.sync.aligned.m16n8k8.row.col.f32.tf32.tf32.f32 "
        "{%0,%1,%2,%3}, {%4,%5,%6,%7}, {%8,%9}, {%0,%1,%2,%3};"
        : "+f"(c[0]), "+f"(c[1]), "+f"(c[2]), "+f"(c[3])
        : "r"(a[0]), "r"(a[1]), "r"(a[2]), "r"(a[3]), "r"(b0), "r"(b1));
}

// ------------------------- tf32 mma.sync GEMM -------------------------------
// BM=BN=128, BK=16, 256 threads (8 warps 2x4), warp tile 64x32 (4x4 atoms).
// 3-stage cp.async pipeline; smem 3 x (A 8KB + B 8KB) = 48KB static.
// Swizzle: 16B chunk ch' = ch ^ ((row>>1)&3), row stride 64B.
#define NITK 32   // 512 / 16

template<bool BIAS, bool CVT, int ASEL, int BSEL, int CSEL>
__global__ __launch_bounds__(256)
void gemm_mma(const float* __restrict__ Ain, const float* __restrict__ Bin,
              float* __restrict__ Cin, const float* __restrict__ bias,
              int lda, int ldb, int ldc,
              size_t sA, size_t sB, size_t sC, float alpha)
{
    __shared__ uint32_t sm[3][2][128 * 16];

    const float* A = pick_c<ASEL>(Ain) + (size_t)blockIdx.z * sA;
    const float* B = pick_c<BSEL>(Bin) + (size_t)blockIdx.z * sB;
    float*       C = pick_m<CSEL>(Cin) + (size_t)blockIdx.z * sC;

    const int m0 = blockIdx.y * 128;
    const int n0 = blockIdx.x * 128;
    const int tid  = threadIdx.x;
    const int warp = tid >> 5, lane = tid & 31;
    const int wm = (warp & 1) * 64;        // warp M offset
    const int wn = (warp >> 1) * 32;       // warp N offset
    const int gid = lane >> 2, tig = lane & 3;
    const int i8 = lane & 7, mtx = lane >> 3;

    const uint32_t smbase = smem_u32(sm);

    // LDSM byte-offset components (within one operand buffer)
    int rowA[4], rsA[4];
#pragma unroll
    for (int am = 0; am < 4; ++am) {
        int r = wm + am * 16 + i8 + ((mtx & 1) << 3);
        rowA[am] = r * 64;
        rsA[am] = (r >> 1) & 3;
    }
    const int csA = mtx >> 1;
    int rowB[2], rsB[2];
#pragma unroll
    for (int bp = 0; bp < 2; ++bp) {
        int r = wn + bp * 16 + i8 + ((mtx >> 1) << 3);
        rowB[bp] = r * 64;
        rsB[bp] = (r >> 1) & 3;
    }
    const int csB = mtx & 1;

    float acc[4][4][4];
#pragma unroll
    for (int i = 0; i < 4; ++i)
#pragma unroll
        for (int j = 0; j < 4; ++j)
#pragma unroll
            for (int r = 0; r < 4; ++r) acc[i][j][r] = 0.f;

    // staging: per stage 512 chunks per operand, 256 threads -> 2 each
    auto stage_tile = [&](int kt, int s) {
        const int k0 = kt * 16;
        const uint32_t bA = smbase + (uint32_t)s * 16384u;
        const uint32_t bB = bA + 8192u;
#pragma unroll
        for (int l = 0; l < 2; ++l) {
            int idx = tid + l * 256;          // 0..511
            int row = idx >> 2, ch = idx & 3;
            uint32_t woff = (uint32_t)(row * 64 + ((ch ^ ((row >> 1) & 3)) << 4));
            CPA16(bA + woff, A + (size_t)(m0 + row) * lda + k0 + ch * 4);
            CPA16(bB + woff, B + (size_t)(n0 + row) * ldb + k0 + ch * 4);
        }
        CPA_COMMIT();
    };

    stage_tile(0, 0);
    stage_tile(1, 1);

    for (int it = 0; it < NITK; ++it) {
        CPA_WAIT1();
        __syncthreads();
        if (it + 2 < NITK) stage_tile(it + 2, (it + 2) % 3);
        else CPA_COMMIT();   // keep wait_group accounting uniform

        const uint32_t bA = smbase + (uint32_t)(it % 3) * 16384u;
        const uint32_t bB = bA + 8192u;
#pragma unroll
        for (int ks = 0; ks < 2; ++ks) {
            uint32_t af[4][4], bf[2][4];
#pragma unroll
            for (int am = 0; am < 4; ++am)
                LDSM_X4(af[am], bA + rowA[am] + (((2 * ks + csA) ^ rsA[am]) << 4));
#pragma unroll
            for (int bp = 0; bp < 2; ++bp)
                LDSM_X4(bf[bp], bB + rowB[bp] + (((2 * ks + csB) ^ rsB[bp]) << 4));
#pragma unroll
            for (int am = 0; am < 4; ++am)
#pragma unroll
                for (int an = 0; an < 4; ++an)
                    mma_tf32(acc[am][an], af[am],
                             bf[an >> 1][(an & 1) * 2], bf[an >> 1][(an & 1) * 2 + 1]);
        }
    }

    // epilogue
#pragma unroll
    for (int am = 0; am < 4; ++am) {
        int row = m0 + wm + am * 16 + gid;
#pragma unroll
        for (int an = 0; an < 4; ++an) {
            int col = n0 + wn + an * 8 + 2 * tig;
            float b0 = 0.f, b1 = 0.f;
            if (BIAS) { b0 = bias[col]; b1 = bias[col + 1]; }
            float2 v0, v1;
            v0.x = acc[am][an][0] * alpha + b0;
            v0.y = acc[am][an][1] * alpha + b1;
            v1.x = acc[am][an][2] * alpha + b0;
            v1.y = acc[am][an][3] * alpha + b1;
            if (CVT) {
                v0.x = roundtf(v0.x); v0.y = roundtf(v0.y);
                v1.x = roundtf(v1.x); v1.y = roundtf(v1.y);
            }
            *reinterpret_cast<float2*>(C + (size_t)row * ldc + col) = v0;
            *reinterpret_cast<float2*>(C + (size_t)(row + 8) * ldc + col) = v1;
        }
    }
}

// ------------------- tf32 round-copy of x_token ----------------------------
__global__ void round_copy(const float4* __restrict__ in)
{
    size_t i = (size_t)blockIdx.x * 256 + threadIdx.x;
    float4 v = in[i];
    v.x = roundtf(v.x); v.y = roundtf(v.y);
    v.z = roundtf(v.z); v.w = roundtf(v.w);
    reinterpret_cast<float4*>(g_xr)[i] = v;
}

// -------------------------- weight transpose (+round) ----------------------
template<int DSTSEL>
__global__ void transpose_k(const float* __restrict__ in, int R, int C)
{
    __shared__ float t[32][33];
    float* out = pick_m<DSTSEL>(nullptr);
    int c0 = blockIdx.x * 32, r0 = blockIdx.y * 32;
    int x = threadIdx.x, y = threadIdx.y;
#pragma unroll
    for (int i = 0; i < 32; i += 8)
        t[y + i][x] = in[(size_t)(r0 + y + i) * C + (c0 + x)];
    __syncthreads();
#pragma unroll
    for (int i = 0; i < 32; i += 8)
        out[(size_t)(c0 + y + i) * R + (r0 + x)] = roundtf(t[x][y + i]);
}

// --------------------- stable counting sort (per batch) --------------------
__global__ void sort_kernel(const int* __restrict__ idx)
{
    int b = blockIdx.x;
    const int* ic = idx + b * SEQ;
    __shared__ int cnt[NCLUST];
    __shared__ int off[NCLUST + 1];
    int t = threadIdx.x;
    if (t < NCLUST) {
        int c = 0;
        for (int i = 0; i < SEQ; ++i) c += (ic[i] == t);
        cnt[t] = c;
    }
    __syncthreads();
    if (t == 0) {
        int a = 0;
        for (int c = 0; c < NCLUST; ++c) { off[c] = a; a += cnt[c]; }
        off[NCLUST] = a;
        for (int c = 0; c <= NCLUST; ++c) g_offs[b * 17 + c] = off[c];
    }
    __syncthreads();
    if (t < NCLUST) {
        int pos = off[t];
        for (int i = 0; i < SEQ; ++i)
            if (ic[i] == t) {
                g_shuffle[b * SEQ + pos] = i;
                g_restore[b * SEQ + i] = pos;
                g_ssorted[b * SEQ + pos] = t;
                pos++;
            }
    }
}

__global__ void ecol_kernel(const float* __restrict__ attn)
{
    int b = blockIdx.y;
    int j = blockIdx.x * 256 + threadIdx.x;
    const int* sh = g_shuffle + b * SEQ;
    int dd = sh[sh[j]];
    g_e[b * SEQ + j] = expf(attn[(size_t)b * SEQ * SEQ + (size_t)dd * SEQ + j]);
}

__global__ void csum_kernel()
{
    int b = blockIdx.y, c = blockIdx.x, d = threadIdx.x;
    const float* vb = g_v + (size_t)b * SEQ * DIM;
    if (c < NCLUST) {
        int j0 = g_offs[b * 17 + c], j1 = g_offs[b * 17 + c + 1];
        float acc = 0.f, se = 0.f;
        for (int j = j0; j < j1; ++j) {
            float w = g_e[b * SEQ + j];
            int row = g_shuffle[b * SEQ + j];
            acc += w * vb[(size_t)row * DIM + d];
            se += w;
        }
        g_wsum[(b * NCLUST + c) * DIM + d] = acc;
        if (d == 0) g_S[b * NCLUST + c] = se;
    } else {
        int p = c - NCLUST;
        float acc = 0.f;
        for (int j = p * 128; j < p * 128 + 128; ++j)
            acc += vb[(size_t)j * DIM + d];
        g_vpart[(b * NCLUST + p) * DIM + d] = acc;
    }
}

__global__ void fcomp_kernel()
{
    int b = blockIdx.y, c = blockIdx.x, d = threadIdx.x;
    float vs = 0.f;
#pragma unroll
    for (int p = 0; p < NCLUST; ++p) vs += g_vpart[(b * NCLUST + p) * DIM + d];
    float w = g_wsum[(b * NCLUST + c) * DIM + d];
    g_f[(b * NCLUST + c) * DIM + d] =
        (w + (EPS_F / (float)SEQ) * vs) / (g_S[b * NCLUST + c] + EPS_F);
}

// out3[b,i,j] = round_tf32( f[ s[b,(r&3)*512+j] ][ r>>2 ] ),  r = restore[b,i]
__global__ void gather_kernel()
{
    __shared__ float sf[NCLUST];
    int b = blockIdx.z, i = blockIdx.y;
    int r = g_restore[b * SEQ + i];
    int d = r >> 2;
    if (threadIdx.x < NCLUST)
        sf[threadIdx.x] = g_f[(b * NCLUST + threadIdx.x) * DIM + d];
    __syncthreads();
    int j = blockIdx.x * 256 + threadIdx.x;
    int cval = g_ssorted[b * SEQ + ((r & 3) << 9) + j];
    g_out3[((size_t)(b * SEQ + i)) * DIM + j] = roundtf(sf[cval]);
}

// ---------------------------------------------------------------------------
extern "C" void kernel_launch(void* const* d_in, const int* in_sizes, int n_in,
                              void* d_out, int out_size)
{
    const float *x_token = nullptr, *Wqk = nullptr, *Wv = nullptr,
                *Wproj = nullptr, *bproj = nullptr;
    const int *idxc = nullptr;
    for (int i = 0; i < n_in; ++i) {
        long s = in_sizes[i];
        if (s == 8388608 && !x_token)      x_token = (const float*)d_in[i];
        else if (s == 16384 && !idxc)      idxc    = (const int*)d_in[i];
        else if (s == 524288 && !Wqk)      Wqk     = (const float*)d_in[i];
        else if (s == 262144) { if (!Wv) Wv = (const float*)d_in[i];
                                else if (!Wproj) Wproj = (const float*)d_in[i]; }
        else if (s == 512 && !bproj)       bproj   = (const float*)d_in[i];
    }
    if (!x_token || !idxc || !Wqk || !Wv || !Wproj || !bproj) return;

    float* xout = (float*)d_out;
    float* attn = xout + (size_t)ROWS * DIM;

    // 0) pre-round operands
    round_copy<<<8192, 256>>>((const float4*)x_token);
    transpose_k<4><<<dim3(1024 / 32, 512 / 32), dim3(32, 8)>>>(Wqk, 512, 1024);
    transpose_k<5><<<dim3(512 / 32, 512 / 32), dim3(32, 8)>>>(Wv, 512, 512);
    transpose_k<6><<<dim3(512 / 32, 512 / 32), dim3(32, 8)>>>(Wproj, 512, 512);

    // 1) qk = xr @ WqkT^T -> g_qk (epilogue-rounded: feeds attn GEMM)
    gemm_mma<false, true, 7, 4, 0><<<dim3(8, 128, 1), 256>>>(
        nullptr, nullptr, nullptr, nullptr, 512, 512, 1024, 0, 0, 0, 1.0f);

    // 2) v = xr @ WvT^T -> g_v (fp32, consumed by csum)
    gemm_mma<false, false, 7, 5, 2><<<dim3(4, 128, 1), 256>>>(
        nullptr, nullptr, nullptr, nullptr, 512, 512, 512, 0, 0, 0, 1.0f);

    // 3) sort
    sort_kernel<<<BATCH, 32>>>(idxc);

    // 4) attn[b] = q[b] @ k[b]^T * SCALE (batched)
    gemm_mma<false, false, 0, 1, -1><<<dim3(16, 16, BATCH), 256>>>(
        nullptr, nullptr, attn, nullptr, 1024, 1024, SEQ,
        (size_t)SEQ * 1024, (size_t)SEQ * 1024, (size_t)SEQ * SEQ, SCALE_F);

    // 5-8) elementwise pipeline
    ecol_kernel<<<dim3(SEQ / 256, BATCH), 256>>>(attn);
    csum_kernel<<<dim3(32, BATCH), DIM>>>();
    fcomp_kernel<<<dim3(NCLUST, BATCH), DIM>>>();
    gather_kernel<<<dim3(DIM / 256, SEQ, BATCH), 256>>>();

    // 9) x_out = out3 @ WprojT^T + bproj
    gemm_mma<true, false, 3, 6, -1><<<dim3(4, 128, 1), 256>>>(
        nullptr, nullptr, xout, bproj, 512, 512, 512, 0, 0, 0, 1.0f);

    (void)out_size;
}

// round 13
// speedup vs baseline: 1.9415x; 1.4083x over previous
#include <cuda_runtime.h>
#include <cuda_fp16.h>
#include <cstdint>

// ---------------------------------------------------------------------------
// CAttention B=8,N=2048,DIM=512. GEMMs: mma.sync m16n8k16 fp16 (fp32 accum),
// cp.async 3-stage pipeline, XOR-swizzled smem, ldmatrix fragments.
// ALL scratch buffers (inputs AND outputs) resolved device-side via template
// selectors -- __device__ symbols must never be passed from host code.
// Canonical GEMM: D[M,N] = alpha * A[M,K] @ B[N,K]^T (+bias), K=512, BK=32.
// ---------------------------------------------------------------------------

#define BATCH 8
#define SEQ   2048
#define DIM   512
#define ROWS  (BATCH*SEQ)
#define NCLUST 16
#define SCALE_F 0.125f
#define EPS_F  1e-6f

// -------------------- scratch ----------------------------------------------
__device__ __half g_xh[(size_t)ROWS * DIM];       // fp16 x_token
__device__ __half g_qk[(size_t)ROWS * 1024];      // fp16 q|k
__device__ __half g_out3[(size_t)ROWS * DIM];     // fp16 gathered rows
__device__ __half g_wqkT[1024 * 512];
__device__ __half g_wvT[512 * 512];
__device__ __half g_wprojT[512 * 512];
__device__ float  g_v[(size_t)ROWS * DIM];        // fp32 v (csum consumer)
__device__ float  g_e[BATCH * SEQ];
__device__ float  g_S[BATCH * NCLUST];
__device__ float  g_wsum[BATCH * NCLUST * DIM];
__device__ float  g_vpart[BATCH * NCLUST * DIM];
__device__ float  g_f[BATCH * NCLUST * DIM];
__device__ int    g_shuffle[BATCH * SEQ];
__device__ int    g_restore[BATCH * SEQ];
__device__ int    g_ssorted[BATCH * SEQ];
__device__ int    g_offs[BATCH * 17];

// half-buffer selectors for GEMM inputs (device-side only)
template<int SEL>
__device__ __forceinline__ const __half* pick_h() {
    if (SEL == 0) return g_qk;
    if (SEL == 1) return g_qk + DIM;
    if (SEL == 3) return g_out3;
    if (SEL == 4) return g_wqkT;
    if (SEL == 5) return g_wvT;
    if (SEL == 6) return g_wprojT;
    return g_xh;   // 7
}
// output selectors: 0 = g_qk (half), 2 = g_v (float), -1 = runtime float ptr
template<int SEL>
__device__ __forceinline__ __half* pick_oh() { return g_qk; }
template<int SEL>
__device__ __forceinline__ float* pick_of(float* p) {
    if (SEL == 2) return g_v;
    return p;
}

__device__ __forceinline__ uint32_t smem_u32(const void* p) {
    uint32_t a;
    asm("{ .reg .u64 t; cvta.to.shared.u64 t, %1; cvt.u32.u64 %0, t; }"
        : "=r"(a) : "l"(p));
    return a;
}

#define LDSM_X4(r, a) \
    asm volatile("ldmatrix.sync.aligned.m8n8.x4.shared.b16 {%0,%1,%2,%3}, [%4];" \
        : "=r"((r)[0]), "=r"((r)[1]), "=r"((r)[2]), "=r"((r)[3]) : "r"(a))
#define CPA16(dst, src) \
    asm volatile("cp.async.cg.shared.global [%0], [%1], 16;" \
        :: "r"(dst), "l"(src) : "memory")
#define CPA_COMMIT() asm volatile("cp.async.commit_group;" ::: "memory")
#define CPA_WAIT1()  asm volatile("cp.async.wait_group 1;" ::: "memory")

__device__ __forceinline__ void mma_f16(float* c, const uint32_t* a,
                                        uint32_t b0, uint32_t b1) {
    asm volatile(
        "mma.sync.aligned.m16n8k16.row.col.f32.f16.f16.f32 "
        "{%0,%1,%2,%3}, {%4,%5,%6,%7}, {%8,%9}, {%0,%1,%2,%3};"
        : "+f"(c[0]), "+f"(c[1]), "+f"(c[2]), "+f"(c[3])
        : "r"(a[0]), "r"(a[1]), "r"(a[2]), "r"(a[3]), "r"(b0), "r"(b1));
}

// ------------------------- fp16 mma.sync GEMM -------------------------------
// BM=BN=128, BK=32 halves, 256 threads (8 warps 2x4), warp tile 64x32.
// 3-stage cp.async pipeline; smem 3 x (A 8KB + B 8KB) = 48KB static.
// Row = 32 halves = 64B; swizzle: 16B chunk ch' = ch ^ ((row>>1)&3).
#define NITK 16   // 512 / 32

template<bool BIAS, bool HALF_OUT, int ASEL, int BSEL, int CSEL>
__global__ __launch_bounds__(256)
void gemm_mma(float* __restrict__ Cin, const float* __restrict__ bias,
              int lda, int ldb, int ldc,
              size_t sA, size_t sB, size_t sC, float alpha)
{
    __shared__ uint32_t sm[3][2][128 * 16];

    const __half* A = pick_h<ASEL>() + (size_t)blockIdx.z * sA;
    const __half* B = pick_h<BSEL>() + (size_t)blockIdx.z * sB;

    const int m0 = blockIdx.y * 128;
    const int n0 = blockIdx.x * 128;
    const int tid  = threadIdx.x;
    const int warp = tid >> 5, lane = tid & 31;
    const int wm = (warp & 1) * 64;
    const int wn = (warp >> 1) * 32;
    const int gid = lane >> 2, tig = lane & 3;
    const int i8 = lane & 7, mtx = lane >> 3;

    const uint32_t smbase = smem_u32(sm);

    // LDSM byte offsets (validated layout; b16 fragment maps derived for k16)
    int rowA[4], rsA[4];
#pragma unroll
    for (int am = 0; am < 4; ++am) {
        int r = wm + am * 16 + i8 + ((mtx & 1) << 3);
        rowA[am] = r * 64;
        rsA[am] = (r >> 1) & 3;
    }
    const int csA = mtx >> 1;
    int rowB[2], rsB[2];
#pragma unroll
    for (int bp = 0; bp < 2; ++bp) {
        int r = wn + bp * 16 + i8 + ((mtx >> 1) << 3);
        rowB[bp] = r * 64;
        rsB[bp] = (r >> 1) & 3;
    }
    const int csB = mtx & 1;

    float acc[4][4][4];
#pragma unroll
    for (int i = 0; i < 4; ++i)
#pragma unroll
        for (int j = 0; j < 4; ++j)
#pragma unroll
            for (int r = 0; r < 4; ++r) acc[i][j][r] = 0.f;

    // staging: 512 16B-chunks per operand per stage, 256 thr -> 2 each
    auto stage_tile = [&](int kt, int s) {
        const int k0 = kt * 32;
        const uint32_t bA = smbase + (uint32_t)s * 16384u;
        const uint32_t bB = bA + 8192u;
#pragma unroll
        for (int l = 0; l < 2; ++l) {
            int idx = tid + l * 256;
            int row = idx >> 2, ch = idx & 3;
            uint32_t woff = (uint32_t)(row * 64 + ((ch ^ ((row >> 1) & 3)) << 4));
            CPA16(bA + woff, A + (size_t)(m0 + row) * lda + k0 + ch * 8);
            CPA16(bB + woff, B + (size_t)(n0 + row) * ldb + k0 + ch * 8);
        }
        CPA_COMMIT();
    };

    stage_tile(0, 0);
    stage_tile(1, 1);

    for (int it = 0; it < NITK; ++it) {
        CPA_WAIT1();
        __syncthreads();
        if (it + 2 < NITK) stage_tile(it + 2, (it + 2) % 3);
        else CPA_COMMIT();   // keep wait_group accounting uniform

        const uint32_t bA = smbase + (uint32_t)(it % 3) * 16384u;
        const uint32_t bB = bA + 8192u;
#pragma unroll
        for (int ks = 0; ks < 2; ++ks) {   // two k16 steps per BK=32
            uint32_t af[4][4], bf[2][4];
#pragma unroll
            for (int am = 0; am < 4; ++am)
                LDSM_X4(af[am], bA + rowA[am] + (((2 * ks + csA) ^ rsA[am]) << 4));
#pragma unroll
            for (int bp = 0; bp < 2; ++bp)
                LDSM_X4(bf[bp], bB + rowB[bp] + (((2 * ks + csB) ^ rsB[bp]) << 4));
#pragma unroll
            for (int am = 0; am < 4; ++am)
#pragma unroll
                for (int an = 0; an < 4; ++an)
                    mma_f16(acc[am][an], af[am],
                            bf[an >> 1][(an & 1) * 2], bf[an >> 1][(an & 1) * 2 + 1]);
        }
    }

    // epilogue (output buffer resolved device-side)
    float*  Cfb = HALF_OUT ? nullptr : pick_of<CSEL>(Cin) + (size_t)blockIdx.z * sC;
    __half* Chb = HALF_OUT ? pick_oh<CSEL>() + (size_t)blockIdx.z * sC : nullptr;
#pragma unroll
    for (int am = 0; am < 4; ++am) {
        int row = m0 + wm + am * 16 + gid;
#pragma unroll
        for (int an = 0; an < 4; ++an) {
            int col = n0 + wn + an * 8 + 2 * tig;
            float b0 = 0.f, b1 = 0.f;
            if (BIAS) { b0 = bias[col]; b1 = bias[col + 1]; }
            float2 v0, v1;
            v0.x = acc[am][an][0] * alpha + b0;
            v0.y = acc[am][an][1] * alpha + b1;
            v1.x = acc[am][an][2] * alpha + b0;
            v1.y = acc[am][an][3] * alpha + b1;
            if (HALF_OUT) {
                *reinterpret_cast<__half2*>(Chb + (size_t)row * ldc + col) =
                    __floats2half2_rn(v0.x, v0.y);
                *reinterpret_cast<__half2*>(Chb + (size_t)(row + 8) * ldc + col) =
                    __floats2half2_rn(v1.x, v1.y);
            } else {
                *reinterpret_cast<float2*>(Cfb + (size_t)row * ldc + col) = v0;
                *reinterpret_cast<float2*>(Cfb + (size_t)(row + 8) * ldc + col) = v1;
            }
        }
    }
}

// ------------------- fp16 convert of x_token --------------------------------
__global__ void conv_x(const float4* __restrict__ in)
{
    size_t i = (size_t)blockIdx.x * 256 + threadIdx.x;
    float4 v = in[i];
    __half2* o = reinterpret_cast<__half2*>(g_xh) + i * 2;
    o[0] = __floats2half2_rn(v.x, v.y);
    o[1] = __floats2half2_rn(v.z, v.w);
}

// -------------------------- weight transpose (fp32 -> fp16 K-major) --------
template<int DSTSEL>
__global__ void transpose_k(const float* __restrict__ in, int R, int C)
{
    __shared__ float t[32][33];
    __half* out = const_cast<__half*>(pick_h<DSTSEL>());
    int c0 = blockIdx.x * 32, r0 = blockIdx.y * 32;
    int x = threadIdx.x, y = threadIdx.y;
#pragma unroll
    for (int i = 0; i < 32; i += 8)
        t[y + i][x] = in[(size_t)(r0 + y + i) * C + (c0 + x)];
    __syncthreads();
#pragma unroll
    for (int i = 0; i < 32; i += 8)
        out[(size_t)(c0 + y + i) * R + (r0 + x)] = __float2half_rn(t[x][y + i]);
}

// --------------------- stable counting sort (per batch) --------------------
__global__ void sort_kernel(const int* __restrict__ idx)
{
    int b = blockIdx.x;
    const int* ic = idx + b * SEQ;
    __shared__ int cnt[NCLUST];
    __shared__ int off[NCLUST + 1];
    int t = threadIdx.x;
    if (t < NCLUST) {
        int c = 0;
        for (int i = 0; i < SEQ; ++i) c += (ic[i] == t);
        cnt[t] = c;
    }
    __syncthreads();
    if (t == 0) {
        int a = 0;
        for (int c = 0; c < NCLUST; ++c) { off[c] = a; a += cnt[c]; }
        off[NCLUST] = a;
        for (int c = 0; c <= NCLUST; ++c) g_offs[b * 17 + c] = off[c];
    }
    __syncthreads();
    if (t < NCLUST) {
        int pos = off[t];
        for (int i = 0; i < SEQ; ++i)
            if (ic[i] == t) {
                g_shuffle[b * SEQ + pos] = i;
                g_restore[b * SEQ + i] = pos;
                g_ssorted[b * SEQ + pos] = t;
                pos++;
            }
    }
}

__global__ void ecol_kernel(const float* __restrict__ attn)
{
    int b = blockIdx.y;
    int j = blockIdx.x * 256 + threadIdx.x;
    const int* sh = g_shuffle + b * SEQ;
    int dd = sh[sh[j]];
    g_e[b * SEQ + j] = expf(attn[(size_t)b * SEQ * SEQ + (size_t)dd * SEQ + j]);
}

__global__ void csum_kernel()
{
    int b = blockIdx.y, c = blockIdx.x, d = threadIdx.x;
    const float* vb = g_v + (size_t)b * SEQ * DIM;
    if (c < NCLUST) {
        int j0 = g_offs[b * 17 + c], j1 = g_offs[b * 17 + c + 1];
        float acc = 0.f, se = 0.f;
        for (int j = j0; j < j1; ++j) {
            float w = g_e[b * SEQ + j];
            int row = g_shuffle[b * SEQ + j];
            acc += w * vb[(size_t)row * DIM + d];
            se += w;
        }
        g_wsum[(b * NCLUST + c) * DIM + d] = acc;
        if (d == 0) g_S[b * NCLUST + c] = se;
    } else {
        int p = c - NCLUST;
        float acc = 0.f;
        for (int j = p * 128; j < p * 128 + 128; ++j)
            acc += vb[(size_t)j * DIM + d];
        g_vpart[(b * NCLUST + p) * DIM + d] = acc;
    }
}

__global__ void fcomp_kernel()
{
    int b = blockIdx.y, c = blockIdx.x, d = threadIdx.x;
    float vs = 0.f;
#pragma unroll
    for (int p = 0; p < NCLUST; ++p) vs += g_vpart[(b * NCLUST + p) * DIM + d];
    float w = g_wsum[(b * NCLUST + c) * DIM + d];
    g_f[(b * NCLUST + c) * DIM + d] =
        (w + (EPS_F / (float)SEQ) * vs) / (g_S[b * NCLUST + c] + EPS_F);
}

// out3[b,i,j] = fp16( f[ s[b,(r&3)*512+j] ][ r>>2 ] ),  r = restore[b,i]
__global__ void gather_kernel()
{
    __shared__ float sf[NCLUST];
    int b = blockIdx.z, i = blockIdx.y;
    int r = g_restore[b * SEQ + i];
    int d = r >> 2;
    if (threadIdx.x < NCLUST)
        sf[threadIdx.x] = g_f[(b * NCLUST + threadIdx.x) * DIM + d];
    __syncthreads();
    int j = blockIdx.x * 256 + threadIdx.x;
    int cval = g_ssorted[b * SEQ + ((r & 3) << 9) + j];
    g_out3[((size_t)(b * SEQ + i)) * DIM + j] = __float2half_rn(sf[cval]);
}

// ---------------------------------------------------------------------------
extern "C" void kernel_launch(void* const* d_in, const int* in_sizes, int n_in,
                              void* d_out, int out_size)
{
    const float *x_token = nullptr, *Wqk = nullptr, *Wv = nullptr,
                *Wproj = nullptr, *bproj = nullptr;
    const int *idxc = nullptr;
    for (int i = 0; i < n_in; ++i) {
        long s = in_sizes[i];
        if (s == 8388608 && !x_token)      x_token = (const float*)d_in[i];
        else if (s == 16384 && !idxc)      idxc    = (const int*)d_in[i];
        else if (s == 524288 && !Wqk)      Wqk     = (const float*)d_in[i];
        else if (s == 262144) { if (!Wv) Wv = (const float*)d_in[i];
                                else if (!Wproj) Wproj = (const float*)d_in[i]; }
        else if (s == 512 && !bproj)       bproj   = (const float*)d_in[i];
    }
    if (!x_token || !idxc || !Wqk || !Wv || !Wproj || !bproj) return;

    float* xout = (float*)d_out;
    float* attn = xout + (size_t)ROWS * DIM;

    // 0) convert operands to fp16 (K-major weights)
    conv_x<<<8192, 256>>>((const float4*)x_token);
    transpose_k<4><<<dim3(1024 / 32, 512 / 32), dim3(32, 8)>>>(Wqk, 512, 1024);
    transpose_k<5><<<dim3(512 / 32, 512 / 32), dim3(32, 8)>>>(Wv, 512, 512);
    transpose_k<6><<<dim3(512 / 32, 512 / 32), dim3(32, 8)>>>(Wproj, 512, 512);

    // 1) qk = xh @ WqkT^T -> g_qk (fp16 out, device-side selected)
    gemm_mma<false, true, 7, 4, 0><<<dim3(8, 128, 1), 256>>>(
        nullptr, nullptr, 512, 512, 1024, 0, 0, 0, 1.0f);

    // 2) v = xh @ WvT^T -> g_v (fp32 out, device-side selected)
    gemm_mma<false, false, 7, 5, 2><<<dim3(4, 128, 1), 256>>>(
        nullptr, nullptr, 512, 512, 512, 0, 0, 0, 1.0f);

    // 3) sort
    sort_kernel<<<BATCH, 32>>>(idxc);

    // 4) attn[b] = q[b] @ k[b]^T * SCALE (batched, fp32 out to d_out)
    gemm_mma<false, false, 0, 1, -1><<<dim3(16, 16, BATCH), 256>>>(
        attn, nullptr, 1024, 1024, SEQ,
        (size_t)SEQ * 1024, (size_t)SEQ * 1024, (size_t)SEQ * SEQ, SCALE_F);

    // 5-8) elementwise pipeline
    ecol_kernel<<<dim3(SEQ / 256, BATCH), 256>>>(attn);
    csum_kernel<<<dim3(32, BATCH), DIM>>>();
    fcomp_kernel<<<dim3(NCLUST, BATCH), DIM>>>();
    gather_kernel<<<dim3(DIM / 256, SEQ, BATCH), 256>>>();

    // 9) x_out = out3 @ WprojT^T + bproj (fp32 out + bias to d_out)
    gemm_mma<true, false, 3, 6, -1><<<dim3(4, 128, 1), 256>>>(
        xout, bproj, 512, 512, 512, 0, 0, 0, 1.0f);

    (void)out_size;
}

// round 16
// speedup vs baseline: 2.4984x; 1.2868x over previous
#include <cuda_runtime.h>
#include <cuda_fp16.h>
#include <cstdint>

// ---------------------------------------------------------------------------
// CAttention B=8,N=2048,DIM=512. GEMMs: mma.sync m16n8k16 fp16 (fp32 accum),
// cp.async 3-stage pipeline, XOR-swizzled smem, ldmatrix fragments.
// This round: parallel stable sort, fused prep/csum/gather, streaming stores.
// Canonical GEMM: D[M,N] = alpha * A[M,K] @ B[N,K]^T (+bias), K=512, BK=32.
// ---------------------------------------------------------------------------

#define BATCH 8
#define SEQ   2048
#define DIM   512
#define ROWS  (BATCH*SEQ)
#define NCLUST 16
#define SCALE_F 0.125f
#define EPS_F  1e-6f

// -------------------- scratch ----------------------------------------------
__device__ __half g_xh[(size_t)ROWS * DIM];
__device__ __half g_qk[(size_t)ROWS * 1024];
__device__ __half g_out3[(size_t)ROWS * DIM];
__device__ __half g_wqkT[1024 * 512];
__device__ __half g_wvT[512 * 512];
__device__ __half g_wprojT[512 * 512];
__device__ float  g_v[(size_t)ROWS * DIM];
__device__ float  g_S[BATCH * NCLUST];
__device__ float  g_wsum[BATCH * NCLUST * DIM];
__device__ float  g_vpart[BATCH * NCLUST * DIM];
__device__ int    g_shuffle[BATCH * SEQ];
__device__ int    g_restore[BATCH * SEQ];
__device__ int    g_ssorted[BATCH * SEQ];
__device__ int    g_offs[BATCH * 17];

template<int SEL>
__device__ __forceinline__ const __half* pick_h() {
    if (SEL == 0) return g_qk;
    if (SEL == 1) return g_qk + DIM;
    if (SEL == 3) return g_out3;
    if (SEL == 4) return g_wqkT;
    if (SEL == 5) return g_wvT;
    if (SEL == 6) return g_wprojT;
    return g_xh;   // 7
}
template<int SEL>
__device__ __forceinline__ __half* pick_oh() { return g_qk; }
template<int SEL>
__device__ __forceinline__ float* pick_of(float* p) {
    if (SEL == 2) return g_v;
    return p;
}

__device__ __forceinline__ uint32_t smem_u32(const void* p) {
    uint32_t a;
    asm("{ .reg .u64 t; cvta.to.shared.u64 t, %1; cvt.u32.u64 %0, t; }"
        : "=r"(a) : "l"(p));
    return a;
}

#define LDSM_X4(r, a) \
    asm volatile("ldmatrix.sync.aligned.m8n8.x4.shared.b16 {%0,%1,%2,%3}, [%4];" \
        : "=r"((r)[0]), "=r"((r)[1]), "=r"((r)[2]), "=r"((r)[3]) : "r"(a))
#define CPA16(dst, src) \
    asm volatile("cp.async.cg.shared.global [%0], [%1], 16;" \
        :: "r"(dst), "l"(src) : "memory")
#define CPA_COMMIT() asm volatile("cp.async.commit_group;" ::: "memory")
#define CPA_WAIT1()  asm volatile("cp.async.wait_group 1;" ::: "memory")
#define STGCS2(addr, vx, vy) \
    asm volatile("st.global.cs.v2.f32 [%0], {%1,%2};" \
        :: "l"(addr), "f"(vx), "f"(vy) : "memory")

__device__ __forceinline__ void mma_f16(float* c, const uint32_t* a,
                                        uint32_t b0, uint32_t b1) {
    asm volatile(
        "mma.sync.aligned.m16n8k16.row.col.f32.f16.f16.f32 "
        "{%0,%1,%2,%3}, {%4,%5,%6,%7}, {%8,%9}, {%0,%1,%2,%3};"
        : "+f"(c[0]), "+f"(c[1]), "+f"(c[2]), "+f"(c[3])
        : "r"(a[0]), "r"(a[1]), "r"(a[2]), "r"(a[3]), "r"(b0), "r"(b1));
}

// ------------------------- fp16 mma.sync GEMM (validated R12) ---------------
#define NITK 16   // 512 / 32

template<bool BIAS, bool HALF_OUT, bool STREAM, int ASEL, int BSEL, int CSEL>
__global__ __launch_bounds__(256)
void gemm_mma(float* __restrict__ Cin, const float* __restrict__ bias,
              int lda, int ldb, int ldc,
              size_t sA, size_t sB, size_t sC, float alpha)
{
    __shared__ uint32_t sm[3][2][128 * 16];

    const __half* A = pick_h<ASEL>() + (size_t)blockIdx.z * sA;
    const __half* B = pick_h<BSEL>() + (size_t)blockIdx.z * sB;

    const int m0 = blockIdx.y * 128;
    const int n0 = blockIdx.x * 128;
    const int tid  = threadIdx.x;
    const int warp = tid >> 5, lane = tid & 31;
    const int wm = (warp & 1) * 64;
    const int wn = (warp >> 1) * 32;
    const int gid = lane >> 2, tig = lane & 3;
    const int i8 = lane & 7, mtx = lane >> 3;

    const uint32_t smbase = smem_u32(sm);

    int rowA[4], rsA[4];
#pragma unroll
    for (int am = 0; am < 4; ++am) {
        int r = wm + am * 16 + i8 + ((mtx & 1) << 3);
        rowA[am] = r * 64;
        rsA[am] = (r >> 1) & 3;
    }
    const int csA = mtx >> 1;
    int rowB[2], rsB[2];
#pragma unroll
    for (int bp = 0; bp < 2; ++bp) {
        int r = wn + bp * 16 + i8 + ((mtx >> 1) << 3);
        rowB[bp] = r * 64;
        rsB[bp] = (r >> 1) & 3;
    }
    const int csB = mtx & 1;

    float acc[4][4][4];
#pragma unroll
    for (int i = 0; i < 4; ++i)
#pragma unroll
        for (int j = 0; j < 4; ++j)
#pragma unroll
            for (int r = 0; r < 4; ++r) acc[i][j][r] = 0.f;

    auto stage_tile = [&](int kt, int s) {
        const int k0 = kt * 32;
        const uint32_t bA = smbase + (uint32_t)s * 16384u;
        const uint32_t bB = bA + 8192u;
#pragma unroll
        for (int l = 0; l < 2; ++l) {
            int idx = tid + l * 256;
            int row = idx >> 2, ch = idx & 3;
            uint32_t woff = (uint32_t)(row * 64 + ((ch ^ ((row >> 1) & 3)) << 4));
            CPA16(bA + woff, A + (size_t)(m0 + row) * lda + k0 + ch * 8);
            CPA16(bB + woff, B + (size_t)(n0 + row) * ldb + k0 + ch * 8);
        }
        CPA_COMMIT();
    };

    stage_tile(0, 0);
    stage_tile(1, 1);

    for (int it = 0; it < NITK; ++it) {
        CPA_WAIT1();
        __syncthreads();
        if (it + 2 < NITK) stage_tile(it + 2, (it + 2) % 3);
        else CPA_COMMIT();

        const uint32_t bA = smbase + (uint32_t)(it % 3) * 16384u;
        const uint32_t bB = bA + 8192u;
#pragma unroll
        for (int ks = 0; ks < 2; ++ks) {
            uint32_t af[4][4], bf[2][4];
#pragma unroll
            for (int am = 0; am < 4; ++am)
                LDSM_X4(af[am], bA + rowA[am] + (((2 * ks + csA) ^ rsA[am]) << 4));
#pragma unroll
            for (int bp = 0; bp < 2; ++bp)
                LDSM_X4(bf[bp], bB + rowB[bp] + (((2 * ks + csB) ^ rsB[bp]) << 4));
#pragma unroll
            for (int am = 0; am < 4; ++am)
#pragma unroll
                for (int an = 0; an < 4; ++an)
                    mma_f16(acc[am][an], af[am],
                            bf[an >> 1][(an & 1) * 2], bf[an >> 1][(an & 1) * 2 + 1]);
        }
    }

    float*  Cfb = HALF_OUT ? nullptr : pick_of<CSEL>(Cin) + (size_t)blockIdx.z * sC;
    __half* Chb = HALF_OUT ? pick_oh<CSEL>() + (size_t)blockIdx.z * sC : nullptr;
#pragma unroll
    for (int am = 0; am < 4; ++am) {
        int row = m0 + wm + am * 16 + gid;
#pragma unroll
        for (int an = 0; an < 4; ++an) {
            int col = n0 + wn + an * 8 + 2 * tig;
            float b0 = 0.f, b1 = 0.f;
            if (BIAS) { b0 = bias[col]; b1 = bias[col + 1]; }
            float2 v0, v1;
            v0.x = acc[am][an][0] * alpha + b0;
            v0.y = acc[am][an][1] * alpha + b1;
            v1.x = acc[am][an][2] * alpha + b0;
            v1.y = acc[am][an][3] * alpha + b1;
            if (HALF_OUT) {
                *reinterpret_cast<__half2*>(Chb + (size_t)row * ldc + col) =
                    __floats2half2_rn(v0.x, v0.y);
                *reinterpret_cast<__half2*>(Chb + (size_t)(row + 8) * ldc + col) =
                    __floats2half2_rn(v1.x, v1.y);
            } else if (STREAM) {
                STGCS2(Cfb + (size_t)row * ldc + col, v0.x, v0.y);
                STGCS2(Cfb + (size_t)(row + 8) * ldc + col, v1.x, v1.y);
            } else {
                *reinterpret_cast<float2*>(Cfb + (size_t)row * ldc + col) = v0;
                *reinterpret_cast<float2*>(Cfb + (size_t)(row + 8) * ldc + col) = v1;
            }
        }
    }
}

// ---------------- prep: x fp16 convert + 3 weight transposes ----------------
// blocks [0,8192): conv_x; [8192,8704): WqkT; [8704,8960): WvT; [8960,9216): WprojT
__device__ __forceinline__ void do_transpose(const float* in, __half* out,
                                             int R, int C, int bx, int by,
                                             float t[32][33])
{
    int c0 = bx * 32, r0 = by * 32;
    int x = threadIdx.x & 31, y = threadIdx.x >> 5;
#pragma unroll
    for (int i = 0; i < 32; i += 8)
        t[y + i][x] = in[(size_t)(r0 + y + i) * C + (c0 + x)];
    __syncthreads();
#pragma unroll
    for (int i = 0; i < 32; i += 8)
        out[(size_t)(c0 + y + i) * R + (r0 + x)] = __float2half_rn(t[x][y + i]);
}

__global__ void prep_kernel(const float4* __restrict__ x4,
                            const float* __restrict__ Wqk,
                            const float* __restrict__ Wv,
                            const float* __restrict__ Wproj)
{
    __shared__ float t[32][33];
    int blk = blockIdx.x;
    if (blk < 8192) {
        size_t i = (size_t)blk * 256 + threadIdx.x;
        float4 v = x4[i];
        __half2* o = reinterpret_cast<__half2*>(g_xh) + i * 2;
        o[0] = __floats2half2_rn(v.x, v.y);
        o[1] = __floats2half2_rn(v.z, v.w);
    } else if (blk < 8704) {
        int b = blk - 8192;                 // 32 x 16
        do_transpose(Wqk, g_wqkT, 512, 1024, b & 31, b >> 5, t);
    } else if (blk < 8960) {
        int b = blk - 8704;                 // 16 x 16
        do_transpose(Wv, g_wvT, 512, 512, b & 15, b >> 4, t);
    } else {
        int b = blk - 8960;
        do_transpose(Wproj, g_wprojT, 512, 512, b & 15, b >> 4, t);
    }
}

// --------------- parallel stable counting sort (per batch) ------------------
// 128 threads, 16 elements each; per-chunk histograms + cluster-major scan.
__global__ __launch_bounds__(128)
void sort_kernel(const int* __restrict__ idx)
{
    __shared__ int hist[128][NCLUST];
    __shared__ int choff[128][NCLUST];
    __shared__ int base[NCLUST + 1];
    int b = blockIdx.x, t = threadIdx.x;
    const int* ic = idx + b * SEQ;

    int h[NCLUST];
#pragma unroll
    for (int c = 0; c < NCLUST; ++c) h[c] = 0;
#pragma unroll
    for (int k = 0; k < 16; ++k) h[ic[t * 16 + k]]++;
#pragma unroll
    for (int c = 0; c < NCLUST; ++c) hist[t][c] = h[c];
    __syncthreads();

    if (t < NCLUST) {
        int run = 0;
        for (int tt = 0; tt < 128; ++tt) { choff[tt][t] = run; run += hist[tt][t]; }
        base[t] = run;                       // total count for cluster t (temp)
    }
    __syncthreads();
    if (t == 0) {
        int a = 0;
        for (int c = 0; c < NCLUST; ++c) { int n = base[c]; base[c] = a; a += n; }
        base[NCLUST] = a;
        for (int c = 0; c <= NCLUST; ++c) g_offs[b * 17 + c] = base[c];
    }
    __syncthreads();

    int pos[NCLUST];
#pragma unroll
    for (int c = 0; c < NCLUST; ++c) pos[c] = base[c] + choff[t][c];
#pragma unroll
    for (int k = 0; k < 16; ++k) {
        int i = t * 16 + k;
        int c = ic[i];
        int p = pos[c]++;
        g_shuffle[b * SEQ + p] = i;
        g_restore[b * SEQ + i] = p;
        g_ssorted[b * SEQ + p] = c;
    }
}

// ---------- csum (with fused e = exp(colvals)): cluster sums + vsum ---------
__global__ __launch_bounds__(512)
void csum_kernel(const float* __restrict__ attn)
{
    __shared__ float se[SEQ];                 // 8KB, worst case
    int b = blockIdx.y, c = blockIdx.x, d = threadIdx.x;
    const float* vb = g_v + (size_t)b * SEQ * DIM;

    if (c < NCLUST) {
        int j0 = g_offs[b * 17 + c], j1 = g_offs[b * 17 + c + 1];
        int L = j1 - j0;
        const int* sh = g_shuffle + b * SEQ;
        for (int jj = d; jj < L; jj += 512) {
            int j = j0 + jj;
            int dd = sh[sh[j]];
            se[jj] = expf(attn[(size_t)b * SEQ * SEQ + (size_t)dd * SEQ + j]);
        }
        __syncthreads();
        float acc = 0.f;
        for (int jj = 0; jj < L; ++jj) {
            int row = sh[j0 + jj];
            acc += se[jj] * vb[(size_t)row * DIM + d];
        }
        g_wsum[(b * NCLUST + c) * DIM + d] = acc;
        if (d < 32) {                         // warp 0 reduces S
            float s = 0.f;
            for (int jj = d; jj < L; jj += 32) s += se[jj];
#pragma unroll
            for (int o = 16; o > 0; o >>= 1)
                s += __shfl_down_sync(0xFFFFFFFF, s, o);
            if (d == 0) g_S[b * NCLUST + c] = s;
        }
    } else {
        int p = c - NCLUST;
        float acc = 0.f;
        for (int j = p * 128; j < p * 128 + 128; ++j)
            acc += vb[(size_t)j * DIM + d];
        g_vpart[(b * NCLUST + p) * DIM + d] = acc;
    }
}

// --------- gather (with fused fcomp): out3[b,i,j] = fp16(f[s..][r>>2]) ------
__global__ void gather_kernel()
{
    __shared__ float sf[NCLUST];
    int b = blockIdx.z, i = blockIdx.y;
    int r = g_restore[b * SEQ + i];
    int d = r >> 2;
    if (threadIdx.x < NCLUST) {
        int c = threadIdx.x;
        float vs = 0.f;
#pragma unroll
        for (int p = 0; p < NCLUST; ++p) vs += g_vpart[(b * NCLUST + p) * DIM + d];
        float w = g_wsum[(b * NCLUST + c) * DIM + d];
        sf[c] = (w + (EPS_F / (float)SEQ) * vs) / (g_S[b * NCLUST + c] + EPS_F);
    }
    __syncthreads();
    int j = blockIdx.x * 256 + threadIdx.x;
    int cval = g_ssorted[b * SEQ + ((r & 3) << 9) + j];
    g_out3[((size_t)(b * SEQ + i)) * DIM + j] = __float2half_rn(sf[cval]);
}

// ---------------------------------------------------------------------------
extern "C" void kernel_launch(void* const* d_in, const int* in_sizes, int n_in,
                              void* d_out, int out_size)
{
    const float *x_token = nullptr, *Wqk = nullptr, *Wv = nullptr,
                *Wproj = nullptr, *bproj = nullptr;
    const int *idxc = nullptr;
    for (int i = 0; i < n_in; ++i) {
        long s = in_sizes[i];
        if (s == 8388608 && !x_token)      x_token = (const float*)d_in[i];
        else if (s == 16384 && !idxc)      idxc    = (const int*)d_in[i];
        else if (s == 524288 && !Wqk)      Wqk     = (const float*)d_in[i];
        else if (s == 262144) { if (!Wv) Wv = (const float*)d_in[i];
                                else if (!Wproj) Wproj = (const float*)d_in[i]; }
        else if (s == 512 && !bproj)       bproj   = (const float*)d_in[i];
    }
    if (!x_token || !idxc || !Wqk || !Wv || !Wproj || !bproj) return;

    float* xout = (float*)d_out;
    float* attn = xout + (size_t)ROWS * DIM;

    // 0) fused prep: x fp16 + K-major fp16 weights
    prep_kernel<<<9216, 256>>>((const float4*)x_token, Wqk, Wv, Wproj);

    // 1) qk = xh @ WqkT^T -> g_qk (fp16)
    gemm_mma<false, true, false, 7, 4, 0><<<dim3(8, 128, 1), 256>>>(
        nullptr, nullptr, 512, 512, 1024, 0, 0, 0, 1.0f);

    // 2) v = xh @ WvT^T -> g_v (fp32)
    gemm_mma<false, false, false, 7, 5, 2><<<dim3(4, 128, 1), 256>>>(
        nullptr, nullptr, 512, 512, 512, 0, 0, 0, 1.0f);

    // 3) parallel stable sort
    sort_kernel<<<BATCH, 128>>>(idxc);

    // 4) attn[b] = q[b] @ k[b]^T * SCALE (streaming fp32 out to d_out)
    gemm_mma<false, false, true, 0, 1, -1><<<dim3(16, 16, BATCH), 256>>>(
        attn, nullptr, 1024, 1024, SEQ,
        (size_t)SEQ * 1024, (size_t)SEQ * 1024, (size_t)SEQ * SEQ, SCALE_F);

    // 5) csum (fused exp) + vsum partials
    csum_kernel<<<dim3(32, BATCH), 512>>>(attn);

    // 6) gather (fused fcomp)
    gather_kernel<<<dim3(DIM / 256, SEQ, BATCH), 256>>>();

    // 7) x_out = out3 @ WprojT^T + bproj (streaming fp32 out + bias)
    gemm_mma<true, false, true, 3, 6, -1><<<dim3(4, 128, 1), 256>>>(
        xout, bproj, 512, 512, 512, 0, 0, 0, 1.0f);

    (void)out_size;
}

// round 17
// speedup vs baseline: 2.6571x; 1.0635x over previous
#include <cuda_runtime.h>
#include <cuda_fp16.h>
#include <cstdint>

// ---------------------------------------------------------------------------
// CAttention B=8,N=2048,DIM=512. GEMMs: mma.sync m16n8k16 fp16 (fp32 accum),
// cp.async 3-stage pipeline, XOR-swizzled smem, ldmatrix fragments.
// This round: warp-parallel sort, un-fused fcomp, ILP'd csum, lean gather.
// Canonical GEMM: D[M,N] = alpha * A[M,K] @ B[N,K]^T (+bias), K=512, BK=32.
// ---------------------------------------------------------------------------

#define BATCH 8
#define SEQ   2048
#define DIM   512
#define ROWS  (BATCH*SEQ)
#define NCLUST 16
#define SCALE_F 0.125f
#define EPS_F  1e-6f

// -------------------- scratch ----------------------------------------------
__device__ __half g_xh[(size_t)ROWS * DIM];
__device__ __half g_qk[(size_t)ROWS * 1024];
__device__ __half g_out3[(size_t)ROWS * DIM];
__device__ __half g_wqkT[1024 * 512];
__device__ __half g_wvT[512 * 512];
__device__ __half g_wprojT[512 * 512];
__device__ float  g_v[(size_t)ROWS * DIM];
__device__ float  g_S[BATCH * NCLUST];
__device__ float  g_wsum[BATCH * NCLUST * DIM];
__device__ float  g_vpart[BATCH * NCLUST * DIM];
__device__ float  g_f[BATCH * NCLUST * DIM];
__device__ int    g_shuffle[BATCH * SEQ];
__device__ int    g_restore[BATCH * SEQ];
__device__ int    g_ssorted[BATCH * SEQ];
__device__ int    g_offs[BATCH * 17];

template<int SEL>
__device__ __forceinline__ const __half* pick_h() {
    if (SEL == 0) return g_qk;
    if (SEL == 1) return g_qk + DIM;
    if (SEL == 3) return g_out3;
    if (SEL == 4) return g_wqkT;
    if (SEL == 5) return g_wvT;
    if (SEL == 6) return g_wprojT;
    return g_xh;   // 7
}
template<int SEL>
__device__ __forceinline__ __half* pick_oh() { return g_qk; }
template<int SEL>
__device__ __forceinline__ float* pick_of(float* p) {
    if (SEL == 2) return g_v;
    return p;
}

__device__ __forceinline__ uint32_t smem_u32(const void* p) {
    uint32_t a;
    asm("{ .reg .u64 t; cvta.to.shared.u64 t, %1; cvt.u32.u64 %0, t; }"
        : "=r"(a) : "l"(p));
    return a;
}

#define LDSM_X4(r, a) \
    asm volatile("ldmatrix.sync.aligned.m8n8.x4.shared.b16 {%0,%1,%2,%3}, [%4];" \
        : "=r"((r)[0]), "=r"((r)[1]), "=r"((r)[2]), "=r"((r)[3]) : "r"(a))
#define CPA16(dst, src) \
    asm volatile("cp.async.cg.shared.global [%0], [%1], 16;" \
        :: "r"(dst), "l"(src) : "memory")
#define CPA_COMMIT() asm volatile("cp.async.commit_group;" ::: "memory")
#define CPA_WAIT1()  asm volatile("cp.async.wait_group 1;" ::: "memory")
#define STGCS2(addr, vx, vy) \
    asm volatile("st.global.cs.v2.f32 [%0], {%1,%2};" \
        :: "l"(addr), "f"(vx), "f"(vy) : "memory")

__device__ __forceinline__ void mma_f16(float* c, const uint32_t* a,
                                        uint32_t b0, uint32_t b1) {
    asm volatile(
        "mma.sync.aligned.m16n8k16.row.col.f32.f16.f16.f32 "
        "{%0,%1,%2,%3}, {%4,%5,%6,%7}, {%8,%9}, {%0,%1,%2,%3};"
        : "+f"(c[0]), "+f"(c[1]), "+f"(c[2]), "+f"(c[3])
        : "r"(a[0]), "r"(a[1]), "r"(a[2]), "r"(a[3]), "r"(b0), "r"(b1));
}

// ------------------------- fp16 mma.sync GEMM (validated) -------------------
#define NITK 16   // 512 / 32

template<bool BIAS, bool HALF_OUT, bool STREAM, int ASEL, int BSEL, int CSEL>
__global__ __launch_bounds__(256)
void gemm_mma(float* __restrict__ Cin, const float* __restrict__ bias,
              int lda, int ldb, int ldc,
              size_t sA, size_t sB, size_t sC, float alpha)
{
    __shared__ uint32_t sm[3][2][128 * 16];

    const __half* A = pick_h<ASEL>() + (size_t)blockIdx.z * sA;
    const __half* B = pick_h<BSEL>() + (size_t)blockIdx.z * sB;

    const int m0 = blockIdx.y * 128;
    const int n0 = blockIdx.x * 128;
    const int tid  = threadIdx.x;
    const int warp = tid >> 5, lane = tid & 31;
    const int wm = (warp & 1) * 64;
    const int wn = (warp >> 1) * 32;
    const int gid = lane >> 2, tig = lane & 3;
    const int i8 = lane & 7, mtx = lane >> 3;

    const uint32_t smbase = smem_u32(sm);

    int rowA[4], rsA[4];
#pragma unroll
    for (int am = 0; am < 4; ++am) {
        int r = wm + am * 16 + i8 + ((mtx & 1) << 3);
        rowA[am] = r * 64;
        rsA[am] = (r >> 1) & 3;
    }
    const int csA = mtx >> 1;
    int rowB[2], rsB[2];
#pragma unroll
    for (int bp = 0; bp < 2; ++bp) {
        int r = wn + bp * 16 + i8 + ((mtx >> 1) << 3);
        rowB[bp] = r * 64;
        rsB[bp] = (r >> 1) & 3;
    }
    const int csB = mtx & 1;

    float acc[4][4][4];
#pragma unroll
    for (int i = 0; i < 4; ++i)
#pragma unroll
        for (int j = 0; j < 4; ++j)
#pragma unroll
            for (int r = 0; r < 4; ++r) acc[i][j][r] = 0.f;

    auto stage_tile = [&](int kt, int s) {
        const int k0 = kt * 32;
        const uint32_t bA = smbase + (uint32_t)s * 16384u;
        const uint32_t bB = bA + 8192u;
#pragma unroll
        for (int l = 0; l < 2; ++l) {
            int idx = tid + l * 256;
            int row = idx >> 2, ch = idx & 3;
            uint32_t woff = (uint32_t)(row * 64 + ((ch ^ ((row >> 1) & 3)) << 4));
            CPA16(bA + woff, A + (size_t)(m0 + row) * lda + k0 + ch * 8);
            CPA16(bB + woff, B + (size_t)(n0 + row) * ldb + k0 + ch * 8);
        }
        CPA_COMMIT();
    };

    stage_tile(0, 0);
    stage_tile(1, 1);

    for (int it = 0; it < NITK; ++it) {
        CPA_WAIT1();
        __syncthreads();
        if (it + 2 < NITK) stage_tile(it + 2, (it + 2) % 3);
        else CPA_COMMIT();

        const uint32_t bA = smbase + (uint32_t)(it % 3) * 16384u;
        const uint32_t bB = bA + 8192u;
#pragma unroll
        for (int ks = 0; ks < 2; ++ks) {
            uint32_t af[4][4], bf[2][4];
#pragma unroll
            for (int am = 0; am < 4; ++am)
                LDSM_X4(af[am], bA + rowA[am] + (((2 * ks + csA) ^ rsA[am]) << 4));
#pragma unroll
            for (int bp = 0; bp < 2; ++bp)
                LDSM_X4(bf[bp], bB + rowB[bp] + (((2 * ks + csB) ^ rsB[bp]) << 4));
#pragma unroll
            for (int am = 0; am < 4; ++am)
#pragma unroll
                for (int an = 0; an < 4; ++an)
                    mma_f16(acc[am][an], af[am],
                            bf[an >> 1][(an & 1) * 2], bf[an >> 1][(an & 1) * 2 + 1]);
        }
    }

    float*  Cfb = HALF_OUT ? nullptr : pick_of<CSEL>(Cin) + (size_t)blockIdx.z * sC;
    __half* Chb = HALF_OUT ? pick_oh<CSEL>() + (size_t)blockIdx.z * sC : nullptr;
#pragma unroll
    for (int am = 0; am < 4; ++am) {
        int row = m0 + wm + am * 16 + gid;
#pragma unroll
        for (int an = 0; an < 4; ++an) {
            int col = n0 + wn + an * 8 + 2 * tig;
            float b0 = 0.f, b1 = 0.f;
            if (BIAS) { b0 = bias[col]; b1 = bias[col + 1]; }
            float2 v0, v1;
            v0.x = acc[am][an][0] * alpha + b0;
            v0.y = acc[am][an][1] * alpha + b1;
            v1.x = acc[am][an][2] * alpha + b0;
            v1.y = acc[am][an][3] * alpha + b1;
            if (HALF_OUT) {
                *reinterpret_cast<__half2*>(Chb + (size_t)row * ldc + col) =
                    __floats2half2_rn(v0.x, v0.y);
                *reinterpret_cast<__half2*>(Chb + (size_t)(row + 8) * ldc + col) =
                    __floats2half2_rn(v1.x, v1.y);
            } else if (STREAM) {
                STGCS2(Cfb + (size_t)row * ldc + col, v0.x, v0.y);
                STGCS2(Cfb + (size_t)(row + 8) * ldc + col, v1.x, v1.y);
            } else {
                *reinterpret_cast<float2*>(Cfb + (size_t)row * ldc + col) = v0;
                *reinterpret_cast<float2*>(Cfb + (size_t)(row + 8) * ldc + col) = v1;
            }
        }
    }
}

// ---------------- prep: x fp16 convert + 3 weight transposes ----------------
__device__ __forceinline__ void do_transpose(const float* in, __half* out,
                                             int R, int C, int bx, int by,
                                             float t[32][33])
{
    int c0 = bx * 32, r0 = by * 32;
    int x = threadIdx.x & 31, y = threadIdx.x >> 5;
#pragma unroll
    for (int i = 0; i < 32; i += 8)
        t[y + i][x] = in[(size_t)(r0 + y + i) * C + (c0 + x)];
    __syncthreads();
#pragma unroll
    for (int i = 0; i < 32; i += 8)
        out[(size_t)(c0 + y + i) * R + (r0 + x)] = __float2half_rn(t[x][y + i]);
}

__global__ void prep_kernel(const float4* __restrict__ x4,
                            const float* __restrict__ Wqk,
                            const float* __restrict__ Wv,
                            const float* __restrict__ Wproj)
{
    __shared__ float t[32][33];
    int blk = blockIdx.x;
    if (blk < 8192) {
        size_t i = (size_t)blk * 256 + threadIdx.x;
        float4 v = x4[i];
        __half2* o = reinterpret_cast<__half2*>(g_xh) + i * 2;
        o[0] = __floats2half2_rn(v.x, v.y);
        o[1] = __floats2half2_rn(v.z, v.w);
    } else if (blk < 8704) {
        int b = blk - 8192;
        do_transpose(Wqk, g_wqkT, 512, 1024, b & 31, b >> 5, t);
    } else if (blk < 8960) {
        int b = blk - 8704;
        do_transpose(Wv, g_wvT, 512, 512, b & 15, b >> 4, t);
    } else {
        int b = blk - 8960;
        do_transpose(Wproj, g_wprojT, 512, 512, b & 15, b >> 4, t);
    }
}

// --------------- warp-parallel stable counting sort (per batch) -------------
// 512 threads: 128 chunk-histograms, then one warp per cluster scans the
// 128 chunk counts via shfl; single-warp base scan; 128 threads scatter.
__global__ __launch_bounds__(512)
void sort_kernel(const int* __restrict__ idx)
{
    __shared__ int hist[128][NCLUST];
    __shared__ int choff[128][NCLUST];
    __shared__ int base[NCLUST + 1];
    __shared__ int tot[NCLUST];
    int b = blockIdx.x, t = threadIdx.x;
    const int* ic = idx + b * SEQ;

    if (t < 128) {
        int h[NCLUST];
#pragma unroll
        for (int c = 0; c < NCLUST; ++c) h[c] = 0;
#pragma unroll
        for (int k = 0; k < 16; ++k) h[ic[t * 16 + k]]++;
#pragma unroll
        for (int c = 0; c < NCLUST; ++c) hist[t][c] = h[c];
    }
    __syncthreads();
    {
        int w = t >> 5, l = t & 31;        // warp w scans cluster w
        int h4[4];
#pragma unroll
        for (int i = 0; i < 4; ++i) h4[i] = hist[l * 4 + i][w];
        int local = h4[0] + h4[1] + h4[2] + h4[3];
        int incl = local;
#pragma unroll
        for (int o = 1; o < 32; o <<= 1) {
            int v = __shfl_up_sync(0xFFFFFFFF, incl, o);
            if (l >= o) incl += v;
        }
        int run = incl - local;
#pragma unroll
        for (int i = 0; i < 4; ++i) { choff[l * 4 + i][w] = run; run += h4[i]; }
        if (l == 31) tot[w] = incl;
    }
    __syncthreads();
    if (t == 0) {
        int a = 0;
        for (int c = 0; c < NCLUST; ++c) { base[c] = a; a += tot[c]; }
        base[NCLUST] = a;
        for (int c = 0; c <= NCLUST; ++c) g_offs[b * 17 + c] = base[c];
    }
    __syncthreads();
    if (t < 128) {
        int pos[NCLUST];
#pragma unroll
        for (int c = 0; c < NCLUST; ++c) pos[c] = base[c] + choff[t][c];
#pragma unroll
        for (int k = 0; k < 16; ++k) {
            int i = t * 16 + k;
            int c = ic[i];
            int p = pos[c]++;
            g_shuffle[b * SEQ + p] = i;
            g_restore[b * SEQ + i] = p;
            g_ssorted[b * SEQ + p] = c;
        }
    }
}

// ---------- csum (fused exp, 4-way ILP): cluster sums + vsum ----------------
__global__ __launch_bounds__(512)
void csum_kernel(const float* __restrict__ attn)
{
    __shared__ float se[SEQ];
    int b = blockIdx.y, c = blockIdx.x, d = threadIdx.x;
    const float* vb = g_v + (size_t)b * SEQ * DIM;

    if (c < NCLUST) {
        int j0 = g_offs[b * 17 + c], j1 = g_offs[b * 17 + c + 1];
        int L = j1 - j0;
        const int* sh = g_shuffle + b * SEQ;
        for (int jj = d; jj < L; jj += 512) {
            int j = j0 + jj;
            int dd = sh[sh[j]];
            se[jj] = expf(attn[(size_t)b * SEQ * SEQ + (size_t)dd * SEQ + j]);
        }
        __syncthreads();
        float a0 = 0.f, a1 = 0.f, a2 = 0.f, a3 = 0.f;
        int jj = 0;
        for (; jj + 4 <= L; jj += 4) {
            int r0 = sh[j0 + jj], r1 = sh[j0 + jj + 1];
            int r2 = sh[j0 + jj + 2], r3 = sh[j0 + jj + 3];
            a0 += se[jj]     * vb[(size_t)r0 * DIM + d];
            a1 += se[jj + 1] * vb[(size_t)r1 * DIM + d];
            a2 += se[jj + 2] * vb[(size_t)r2 * DIM + d];
            a3 += se[jj + 3] * vb[(size_t)r3 * DIM + d];
        }
        for (; jj < L; ++jj)
            a0 += se[jj] * vb[(size_t)sh[j0 + jj] * DIM + d];
        g_wsum[(b * NCLUST + c) * DIM + d] = (a0 + a1) + (a2 + a3);
        if (d < 32) {
            float s = 0.f;
            for (int k = d; k < L; k += 32) s += se[k];
#pragma unroll
            for (int o = 16; o > 0; o >>= 1)
                s += __shfl_down_sync(0xFFFFFFFF, s, o);
            if (d == 0) g_S[b * NCLUST + c] = s;
        }
    } else {
        int p = c - NCLUST;
        float acc = 0.f;
        for (int j = p * 128; j < p * 128 + 128; ++j)
            acc += vb[(size_t)j * DIM + d];
        g_vpart[(b * NCLUST + p) * DIM + d] = acc;
    }
}

// ------------- fcomp: f[c][d] = (wsum + eps/N*vsum)/(S+eps) -----------------
__global__ __launch_bounds__(512)
void fcomp_kernel()
{
    int b = blockIdx.y, c = blockIdx.x, d = threadIdx.x;
    float vs = 0.f;
#pragma unroll
    for (int p = 0; p < NCLUST; ++p) vs += g_vpart[(b * NCLUST + p) * DIM + d];
    float w = g_wsum[(b * NCLUST + c) * DIM + d];
    g_f[(b * NCLUST + c) * DIM + d] =
        (w + (EPS_F / (float)SEQ) * vs) / (g_S[b * NCLUST + c] + EPS_F);
}

// --------- gather: out3[b,i,j] = fp16( f[ s[b,(r&3)*512+j] ][ r>>2 ] ) ------
__global__ __launch_bounds__(512)
void gather_kernel()
{
    __shared__ float sf[NCLUST];
    int b = blockIdx.y, i = blockIdx.x;
    int r = g_restore[b * SEQ + i];
    int d = r >> 2;
    if (threadIdx.x < NCLUST)
        sf[threadIdx.x] = g_f[(b * NCLUST + threadIdx.x) * DIM + d];
    __syncthreads();
    int j = threadIdx.x;
    int cval = g_ssorted[b * SEQ + ((r & 3) << 9) + j];
    g_out3[((size_t)(b * SEQ + i)) * DIM + j] = __float2half_rn(sf[cval]);
}

// ---------------------------------------------------------------------------
extern "C" void kernel_launch(void* const* d_in, const int* in_sizes, int n_in,
                              void* d_out, int out_size)
{
    const float *x_token = nullptr, *Wqk = nullptr, *Wv = nullptr,
                *Wproj = nullptr, *bproj = nullptr;
    const int *idxc = nullptr;
    for (int i = 0; i < n_in; ++i) {
        long s = in_sizes[i];
        if (s == 8388608 && !x_token)      x_token = (const float*)d_in[i];
        else if (s == 16384 && !idxc)      idxc    = (const int*)d_in[i];
        else if (s == 524288 && !Wqk)      Wqk     = (const float*)d_in[i];
        else if (s == 262144) { if (!Wv) Wv = (const float*)d_in[i];
                                else if (!Wproj) Wproj = (const float*)d_in[i]; }
        else if (s == 512 && !bproj)       bproj   = (const float*)d_in[i];
    }
    if (!x_token || !idxc || !Wqk || !Wv || !Wproj || !bproj) return;

    float* xout = (float*)d_out;
    float* attn = xout + (size_t)ROWS * DIM;

    // 0) fused prep: x fp16 + K-major fp16 weights
    prep_kernel<<<9216, 256>>>((const float4*)x_token, Wqk, Wv, Wproj);

    // 1) qk = xh @ WqkT^T -> g_qk (fp16)
    gemm_mma<false, true, false, 7, 4, 0><<<dim3(8, 128, 1), 256>>>(
        nullptr, nullptr, 512, 512, 1024, 0, 0, 0, 1.0f);

    // 2) v = xh @ WvT^T -> g_v (fp32)
    gemm_mma<false, false, false, 7, 5, 2><<<dim3(4, 128, 1), 256>>>(
        nullptr, nullptr, 512, 512, 512, 0, 0, 0, 1.0f);

    // 3) warp-parallel stable sort
    sort_kernel<<<BATCH, 512>>>(idxc);

    // 4) attn[b] = q[b] @ k[b]^T * SCALE (streaming fp32 out to d_out)
    gemm_mma<false, false, true, 0, 1, -1><<<dim3(16, 16, BATCH), 256>>>(
        attn, nullptr, 1024, 1024, SEQ,
        (size_t)SEQ * 1024, (size_t)SEQ * 1024, (size_t)SEQ * SEQ, SCALE_F);

    // 5) csum (fused exp) + vsum partials
    csum_kernel<<<dim3(32, BATCH), 512>>>(attn);

    // 6) fcomp (tiny)
    fcomp_kernel<<<dim3(NCLUST, BATCH), 512>>>();

    // 7) gather
    gather_kernel<<<dim3(SEQ, BATCH), 512>>>();

    // 8) x_out = out3 @ WprojT^T + bproj (streaming fp32 out + bias)
    gemm_mma<true, false, true, 3, 6, -1><<<dim3(4, 128, 1), 256>>>(
        xout, bproj, 512, 512, 512, 0, 0, 0, 1.0f);

    (void)out_size;
}